// round 8
// baseline (speedup 1.0000x reference)
#include <cuda_runtime.h>
#include <cuda_bf16.h>
#include <mma.h>
#include <cstdint>

using namespace nvcuda;

// Problem constants
#define BB 4
#define NN 4096
#define DIMM 1024
#define HH 16
#define HDD 64
#define MM (BB * NN)           // 16384 rows
#define NKVC 8                 // kv partial chunks

// ---------------- scratch (device globals; no allocation allowed) ----------
__device__ float g_Q[(size_t)MM * DIMM];
__device__ float g_K[(size_t)MM * DIMM];
__device__ float g_V[(size_t)MM * DIMM];
__device__ float g_A[(size_t)MM * DIMM];
__device__ float g_kvp[(size_t)NKVC * BB * HH * HDD * HDD];   // partial kv
__device__ float g_ksp[(size_t)NKVC * BB * HH * HDD];         // partial ksum

__device__ __forceinline__ float to_tf32(float x) {
    float r;
    asm("cvt.rna.tf32.f32 %0, %1;" : "=f"(r) : "f"(x));
    return r;
}

__device__ __forceinline__ void cp_async16(void* smem_ptr, const void* gmem_ptr) {
    unsigned int s = (unsigned int)__cvta_generic_to_shared(smem_ptr);
    asm volatile("cp.async.cg.shared.global [%0], [%1], 16;\n" :: "r"(s), "l"(gmem_ptr));
}

// ---------------- GEMM: C[m,j] = act( A[m,:] . W[j,:] + bias[j] ) ----------
// M=16384, N=1024, K=1024. Block 128x128, K-step 16, 3-stage cp.async.
// BOTH A and W fragments are rounded to tf32 (RN) in registers -> exact MMA.
#define KS 16
#define LDS_PAD 20                       // 16 + 4 floats
#define TILE_FLOATS (128 * LDS_PAD)      // 2560
#define STAGE_FLOATS (2 * TILE_FLOATS)   // A + B = 5120
#define GSTAGES 3
#define DSMEM_BYTES (GSTAGES * STAGE_FLOATS * 4)   // 61440

extern __shared__ __align__(16) float dsm[];

__global__ void __launch_bounds__(256, 2)
gemm_bias_act(const float* __restrict__ A, const float* __restrict__ W,
              const float* __restrict__ bias, const int* __restrict__ mask,
              float* __restrict__ C, int do_relu) {
    const int t = threadIdx.x;
    const int n0 = blockIdx.x * 128;
    const int m0 = blockIdx.y * 128;
    const int w = t >> 5;
    const int wm = w >> 1;   // 0..3 -> rows wm*32
    const int wn = w & 1;    // 0..1 -> cols wn*64

    wmma::fragment<wmma::accumulator, 16, 16, 8, float> acc[2][4];
#pragma unroll
    for (int i = 0; i < 2; i++)
#pragma unroll
        for (int j = 0; j < 4; j++)
            wmma::fill_fragment(acc[i][j], 0.0f);

    const int u0 = t;            // float4 id 0..255
    const int u1 = t + 256;      // 256..511
    const int rA0 = u0 >> 2, cA0 = (u0 & 3) * 4;
    const int rA1 = u1 >> 2, cA1 = (u1 & 3) * 4;

    const float* Abase = A + (size_t)m0 * DIMM;
    const float* Bbase = W + (size_t)n0 * DIMM;

    auto load_chunk = [&](int c, int s) {
        float* As = dsm + s * STAGE_FLOATS;
        float* Bs = As + TILE_FLOATS;
        const int k0 = c * KS;
        cp_async16(&As[rA0 * LDS_PAD + cA0], Abase + (size_t)rA0 * DIMM + k0 + cA0);
        cp_async16(&As[rA1 * LDS_PAD + cA1], Abase + (size_t)rA1 * DIMM + k0 + cA1);
        cp_async16(&Bs[rA0 * LDS_PAD + cA0], Bbase + (size_t)rA0 * DIMM + k0 + cA0);
        cp_async16(&Bs[rA1 * LDS_PAD + cA1], Bbase + (size_t)rA1 * DIMM + k0 + cA1);
    };

    // prologue: chunks 0 and 1
    load_chunk(0, 0);
    asm volatile("cp.async.commit_group;\n");
    load_chunk(1, 1);
    asm volatile("cp.async.commit_group;\n");

    const int NCH = DIMM / KS;   // 64
    for (int i = 0; i < NCH; i++) {
        const int s = i % GSTAGES;
        asm volatile("cp.async.wait_group 1;\n");
        __syncthreads();

        // issue chunk i+2 into buffer (i+2)%3 (held chunk i-1, already done)
        if (i + 2 < NCH) load_chunk(i + 2, (i + 2) % GSTAGES);
        asm volatile("cp.async.commit_group;\n");

        const float* As = dsm + s * STAGE_FLOATS;
        const float* Bs = As + TILE_FLOATS;
#pragma unroll
        for (int kk = 0; kk < KS; kk += 8) {
            wmma::fragment<wmma::matrix_a, 16, 16, 8, wmma::precision::tf32, wmma::row_major> af[2];
            wmma::fragment<wmma::matrix_b, 16, 16, 8, wmma::precision::tf32, wmma::col_major> bf[4];
#pragma unroll
            for (int i2 = 0; i2 < 2; i2++) {
                wmma::load_matrix_sync(af[i2], As + (wm * 32 + i2 * 16) * LDS_PAD + kk, LDS_PAD);
#pragma unroll
                for (int e = 0; e < af[i2].num_elements; e++)
                    af[i2].x[e] = to_tf32(af[i2].x[e]);
            }
#pragma unroll
            for (int j = 0; j < 4; j++) {
                wmma::load_matrix_sync(bf[j], Bs + (wn * 64 + j * 16) * LDS_PAD + kk, LDS_PAD);
#pragma unroll
                for (int e = 0; e < bf[j].num_elements; e++)
                    bf[j].x[e] = to_tf32(bf[j].x[e]);
            }
#pragma unroll
            for (int i2 = 0; i2 < 2; i2++)
#pragma unroll
                for (int j = 0; j < 4; j++)
                    wmma::mma_sync(acc[i2][j], af[i2], bf[j], acc[i2][j]);
        }
        __syncthreads();
    }

    // ---- epilogue in two 64-row halves through smem (ldm 132, padded) ----
    float* Ct = dsm;   // 64*132 = 8448 floats <= 15360
#pragma unroll
    for (int half = 0; half < 2; half++) {
        if ((wm >> 1) == half) {
            const int wml = wm & 1;
#pragma unroll
            for (int i = 0; i < 2; i++)
#pragma unroll
                for (int j = 0; j < 4; j++)
                    wmma::store_matrix_sync(Ct + (wml * 32 + i * 16) * 132 + wn * 64 + j * 16,
                                            acc[i][j], 132, wmma::mem_row_major);
        }
        __syncthreads();
#pragma unroll
        for (int i = 0; i < 8; i++) {
            int u = t + i * 256;
            int r = u >> 5;
            int c = (u & 31) * 4;
            int row = m0 + half * 64 + r;
            float4 v = *(float4*)(Ct + r * 132 + c);
            v.x += bias[n0 + c + 0];
            v.y += bias[n0 + c + 1];
            v.z += bias[n0 + c + 2];
            v.w += bias[n0 + c + 3];
            if (do_relu) {
                v.x = fmaxf(v.x, 0.0f); v.y = fmaxf(v.y, 0.0f);
                v.z = fmaxf(v.z, 0.0f); v.w = fmaxf(v.w, 0.0f);
            }
            if (mask != nullptr && mask[row] != 0) {
                v.x = 0.0f; v.y = 0.0f; v.z = 0.0f; v.w = 0.0f;
            }
            *(float4*)(C + (size_t)row * DIMM + n0 + c) = v;
        }
        __syncthreads();
    }
}

// ---- kv partials: kvp[c][bh][d][e] = sum_{n in chunk c} K*V ; ksp too ----
__global__ void __launch_bounds__(256)
kv_kernel(const float* __restrict__ K, const float* __restrict__ V,
          float* __restrict__ kvp, float* __restrict__ ksp) {
    const int bh = blockIdx.y;
    const int b = bh >> 4, h = bh & 15;
    const int chunk = blockIdx.x;
    const int t = threadIdx.x;
    __shared__ float ks[4][64];
    __shared__ float vs[4][64];

    const int td = (t >> 4) << 2;
    const int te = (t & 15) << 2;
    float acc[4][4] = {};
    float ksacc = 0.0f;

    const int nbase0 = chunk * 512;
    for (int nb = 0; nb < 512; nb += 4) {
        const int n0 = nbase0 + nb;
#pragma unroll
        for (int j = 0; j < 2; j++) {
            int u = t + j * 256;
            int nn = (u >> 6) & 3;
            int d = u & 63;
            if (u < 256) {
                ks[nn][d] = K[((size_t)(b * NN + n0 + nn)) * DIMM + h * HDD + d];
            } else {
                vs[nn][d] = V[((size_t)(b * NN + n0 + nn)) * DIMM + h * HDD + d];
            }
        }
        __syncthreads();
#pragma unroll
        for (int nn = 0; nn < 4; nn++) {
            float kd0 = ks[nn][td + 0], kd1 = ks[nn][td + 1];
            float kd2 = ks[nn][td + 2], kd3 = ks[nn][td + 3];
            float ve0 = vs[nn][te + 0], ve1 = vs[nn][te + 1];
            float ve2 = vs[nn][te + 2], ve3 = vs[nn][te + 3];
            acc[0][0] += kd0 * ve0; acc[0][1] += kd0 * ve1; acc[0][2] += kd0 * ve2; acc[0][3] += kd0 * ve3;
            acc[1][0] += kd1 * ve0; acc[1][1] += kd1 * ve1; acc[1][2] += kd1 * ve2; acc[1][3] += kd1 * ve3;
            acc[2][0] += kd2 * ve0; acc[2][1] += kd2 * ve1; acc[2][2] += kd2 * ve2; acc[2][3] += kd2 * ve3;
            acc[3][0] += kd3 * ve0; acc[3][1] += kd3 * ve1; acc[3][2] += kd3 * ve2; acc[3][3] += kd3 * ve3;
        }
        if (t < 64) ksacc += ks[0][t] + ks[1][t] + ks[2][t] + ks[3][t];
        __syncthreads();
    }

    float* kvdst = kvp + ((size_t)chunk * 64 + bh) * (HDD * HDD);
#pragma unroll
    for (int i = 0; i < 4; i++)
#pragma unroll
        for (int j = 0; j < 4; j++)
            kvdst[(td + i) * HDD + te + j] = acc[i][j];
    if (t < 64) ksp[((size_t)chunk * 64 + bh) * HDD + t] = ksacc;
}

// ---------------- out = (q.kv) / (q.ksum + eps) -------
__global__ void __launch_bounds__(256)
attn_kernel(const float* __restrict__ Q, const float* __restrict__ kvp,
            const float* __restrict__ ksp, float* __restrict__ out) {
    const int bh = blockIdx.y;
    const int b = bh >> 4, h = bh & 15;
    const int t = threadIdx.x;
    const int w = t >> 5, l = t & 31;

    __shared__ float kvs[64 * 64];
    __shared__ float kss[64];
    __shared__ float qs[8][64];

    for (int i = t; i < 4096; i += 256) {
        float s = 0.0f;
#pragma unroll
        for (int c = 0; c < NKVC; c++)
            s += kvp[((size_t)c * 64 + bh) * 4096 + i];
        kvs[i] = s;
    }
    if (t < 64) {
        float s = 0.0f;
#pragma unroll
        for (int c = 0; c < NKVC; c++)
            s += ksp[((size_t)c * 64 + bh) * 64 + t];
        kss[t] = s;
    }
    __syncthreads();

    const int nbase = blockIdx.x * 128;
    for (int it = 0; it < 16; it++) {
        const int n = nbase + it * 8 + w;
        const float* qrow = Q + ((size_t)(b * NN + n)) * DIMM + h * HDD;
        float q0 = qrow[l];
        float q1 = qrow[l + 32];
        qs[w][l] = q0;
        qs[w][l + 32] = q1;
        __syncwarp();

        float p = q0 * kss[l] + q1 * kss[l + 32];
#pragma unroll
        for (int off = 16; off; off >>= 1) p += __shfl_xor_sync(0xffffffffu, p, off);
        const float denom = 1.0f / (p + 1e-6f);

        float a0 = 0.0f, a1 = 0.0f;
#pragma unroll 8
        for (int d = 0; d < 64; d++) {
            float qd = qs[w][d];
            a0 += qd * kvs[d * 64 + l];
            a1 += qd * kvs[d * 64 + l + 32];
        }
        float* orow = out + ((size_t)(b * NN + n)) * DIMM + h * HDD;
        orow[l] = a0 * denom;
        orow[l + 32] = a1 * denom;
        __syncwarp();
    }
}

// ---------------- launch ----------------
extern "C" void kernel_launch(void* const* d_in, const int* in_sizes, int n_in,
                              void* d_out, int out_size) {
    const float* query = (const float*)d_in[0];
    const float* key   = (const float*)d_in[1];
    const float* value = (const float*)d_in[2];
    const float* Wq = (const float*)d_in[3];
    const float* bq = (const float*)d_in[4];
    const float* Wk = (const float*)d_in[5];
    const float* bk = (const float*)d_in[6];
    const float* Wv = (const float*)d_in[7];
    const float* bv = (const float*)d_in[8];
    const float* Wo = (const float*)d_in[9];
    const float* bo = (const float*)d_in[10];
    const int* mask = (const int*)d_in[11];

    float *Qp, *Kp, *Vp, *Ap, *KVp, *KSp;
    cudaGetSymbolAddress((void**)&Qp, g_Q);
    cudaGetSymbolAddress((void**)&Kp, g_K);
    cudaGetSymbolAddress((void**)&Vp, g_V);
    cudaGetSymbolAddress((void**)&Ap, g_A);
    cudaGetSymbolAddress((void**)&KVp, g_kvp);
    cudaGetSymbolAddress((void**)&KSp, g_ksp);

    cudaFuncSetAttribute(gemm_bias_act, cudaFuncAttributeMaxDynamicSharedMemorySize, DSMEM_BYTES);

    dim3 ggrid(DIMM / 128, MM / 128);   // (8, 128); n-fast for A-tile L2 reuse

    gemm_bias_act<<<ggrid, 256, DSMEM_BYTES>>>(query, Wq, bq, nullptr, Qp, 1);
    gemm_bias_act<<<ggrid, 256, DSMEM_BYTES>>>(key,   Wk, bk, mask,    Kp, 1);
    gemm_bias_act<<<ggrid, 256, DSMEM_BYTES>>>(value, Wv, bv, nullptr, Vp, 0);

    kv_kernel<<<dim3(NKVC, 64), 256>>>(Kp, Vp, KVp, KSp);
    attn_kernel<<<dim3(32, 64), 256>>>(Qp, KVp, KSp, Ap);

    gemm_bias_act<<<ggrid, 256, DSMEM_BYTES>>>(Ap, Wo, bo, nullptr, (float*)d_out, 0);
}

// round 9
// speedup vs baseline: 1.1879x; 1.1879x over previous
#include <cuda_runtime.h>
#include <cuda_bf16.h>
#include <mma.h>
#include <cstdint>

using namespace nvcuda;

// Problem constants
#define BB 4
#define NN 4096
#define DIMM 1024
#define HH 16
#define HDD 64
#define MM (BB * NN)           // 16384 rows
#define KVC 16                 // kv partial chunks

// ---------------- scratch (device globals; no allocation allowed) ----------
__device__ float g_Q[(size_t)MM * DIMM];
__device__ float g_K[(size_t)MM * DIMM];
__device__ float g_V[(size_t)MM * DIMM];
__device__ float g_A[(size_t)MM * DIMM];
__device__ float g_Wr[4 * DIMM * DIMM];
__device__ float g_kvp[(size_t)KVC * BB * HH * HDD * HDD];   // partial kv (16MB)
__device__ float g_ksp[(size_t)KVC * BB * HH * HDD];
__device__ float g_kv[BB * HH * HDD * HDD];
__device__ float g_ksum[BB * HH * HDD];

__device__ __forceinline__ float to_tf32(float x) {
    float r;
    asm("cvt.rna.tf32.f32 %0, %1;" : "=f"(r) : "f"(x));
    return r;
}

__device__ __forceinline__ void cp_async16(void* smem_ptr, const void* gmem_ptr) {
    unsigned int s = (unsigned int)__cvta_generic_to_shared(smem_ptr);
    asm volatile("cp.async.cg.shared.global [%0], [%1], 16;\n" :: "r"(s), "l"(gmem_ptr));
}

// ---------------- fused tf32 rounding of all 4 weight matrices ------------
__global__ void round_w4(const float* __restrict__ W0, const float* __restrict__ W1,
                         const float* __restrict__ W2, const float* __restrict__ W3,
                         float* __restrict__ dst) {
    const float* srcs[4] = {W0, W1, W2, W3};
    const int m = blockIdx.y;
    const float4* s = (const float4*)srcs[m];
    float4* d = (float4*)(dst + (size_t)m * DIMM * DIMM);
    int i = blockIdx.x * blockDim.x + threadIdx.x;
    if (i < (DIMM * DIMM) / 4) {
        float4 v = s[i];
        v.x = to_tf32(v.x); v.y = to_tf32(v.y);
        v.z = to_tf32(v.z); v.w = to_tf32(v.w);
        d[i] = v;
    }
}

// ---------------- GEMM: C[m,j] = act( A[m,:] . W[j,:] + bias[j] ) ----------
// R7-proven shape: 128x128 block, K-step 16, 2-stage cp.async, 2 CTA/SM.
// W pre-rounded tf32; A rounded in fragment registers (RN) -> exact MMA.
#define KS 16
#define LDS_PAD 20
#define STAGE_FLOATS (128 * LDS_PAD)

__global__ void __launch_bounds__(256, 2)
gemm_bias_act(const float* __restrict__ A, const float* __restrict__ W,
              const float* __restrict__ bias, const int* __restrict__ mask,
              float* __restrict__ C, int do_relu) {
    __shared__ __align__(16) float smem[2][2][STAGE_FLOATS];

    const int t = threadIdx.x;
    const int n0 = blockIdx.x * 128;
    const int m0 = blockIdx.y * 128;
    const int w = t >> 5;
    const int wm = w >> 1;
    const int wn = w & 1;

    wmma::fragment<wmma::accumulator, 16, 16, 8, float> acc[2][4];
#pragma unroll
    for (int i = 0; i < 2; i++)
#pragma unroll
        for (int j = 0; j < 4; j++)
            wmma::fill_fragment(acc[i][j], 0.0f);

    const int u0 = t;
    const int u1 = t + 256;
    const int rA0 = u0 >> 2, cA0 = (u0 & 3) * 4;
    const int rA1 = u1 >> 2, cA1 = (u1 & 3) * 4;

    const float* Abase = A + (size_t)m0 * DIMM;
    const float* Bbase = W + (size_t)n0 * DIMM;

    {
        cp_async16(&smem[0][0][rA0 * LDS_PAD + cA0], Abase + (size_t)rA0 * DIMM + cA0);
        cp_async16(&smem[0][0][rA1 * LDS_PAD + cA1], Abase + (size_t)rA1 * DIMM + cA1);
        cp_async16(&smem[0][1][rA0 * LDS_PAD + cA0], Bbase + (size_t)rA0 * DIMM + cA0);
        cp_async16(&smem[0][1][rA1 * LDS_PAD + cA1], Bbase + (size_t)rA1 * DIMM + cA1);
        asm volatile("cp.async.commit_group;\n");
    }

    const int NSTG = DIMM / KS;   // 64
    for (int s = 0; s < NSTG; s++) {
        const int cur = s & 1;
        if (s + 1 < NSTG) {
            const int nxt = cur ^ 1;
            const int k0 = (s + 1) * KS;
            cp_async16(&smem[nxt][0][rA0 * LDS_PAD + cA0], Abase + (size_t)rA0 * DIMM + k0 + cA0);
            cp_async16(&smem[nxt][0][rA1 * LDS_PAD + cA1], Abase + (size_t)rA1 * DIMM + k0 + cA1);
            cp_async16(&smem[nxt][1][rA0 * LDS_PAD + cA0], Bbase + (size_t)rA0 * DIMM + k0 + cA0);
            cp_async16(&smem[nxt][1][rA1 * LDS_PAD + cA1], Bbase + (size_t)rA1 * DIMM + k0 + cA1);
            asm volatile("cp.async.commit_group;\n");
            asm volatile("cp.async.wait_group 1;\n");
        } else {
            asm volatile("cp.async.wait_group 0;\n");
        }
        __syncthreads();

        const float* As = smem[cur][0];
        const float* Bs = smem[cur][1];
#pragma unroll
        for (int kk = 0; kk < KS; kk += 8) {
            wmma::fragment<wmma::matrix_a, 16, 16, 8, wmma::precision::tf32, wmma::row_major> af[2];
            wmma::fragment<wmma::matrix_b, 16, 16, 8, wmma::precision::tf32, wmma::col_major> bf[4];
#pragma unroll
            for (int i = 0; i < 2; i++) {
                wmma::load_matrix_sync(af[i], As + (wm * 32 + i * 16) * LDS_PAD + kk, LDS_PAD);
#pragma unroll
                for (int e = 0; e < af[i].num_elements; e++)
                    af[i].x[e] = to_tf32(af[i].x[e]);
            }
#pragma unroll
            for (int j = 0; j < 4; j++)
                wmma::load_matrix_sync(bf[j], Bs + (wn * 64 + j * 16) * LDS_PAD + kk, LDS_PAD);
#pragma unroll
            for (int i = 0; i < 2; i++)
#pragma unroll
                for (int j = 0; j < 4; j++)
                    wmma::mma_sync(acc[i][j], af[i], bf[j], acc[i][j]);
        }
        __syncthreads();
    }

    float* Ct = &smem[0][0][0];
#pragma unroll
    for (int half = 0; half < 2; half++) {
        if ((wm >> 1) == half) {
            const int wml = wm & 1;
#pragma unroll
            for (int i = 0; i < 2; i++)
#pragma unroll
                for (int j = 0; j < 4; j++)
                    wmma::store_matrix_sync(Ct + (wml * 32 + i * 16) * 132 + wn * 64 + j * 16,
                                            acc[i][j], 132, wmma::mem_row_major);
        }
        __syncthreads();
#pragma unroll
        for (int i = 0; i < 8; i++) {
            int u = t + i * 256;
            int r = u >> 5;
            int c = (u & 31) * 4;
            int row = m0 + half * 64 + r;
            float4 v = *(float4*)(Ct + r * 132 + c);
            v.x += bias[n0 + c + 0];
            v.y += bias[n0 + c + 1];
            v.z += bias[n0 + c + 2];
            v.w += bias[n0 + c + 3];
            if (do_relu) {
                v.x = fmaxf(v.x, 0.0f); v.y = fmaxf(v.y, 0.0f);
                v.z = fmaxf(v.z, 0.0f); v.w = fmaxf(v.w, 0.0f);
            }
            if (mask != nullptr && mask[row] != 0) {
                v.x = 0.0f; v.y = 0.0f; v.z = 0.0f; v.w = 0.0f;
            }
            *(float4*)(C + (size_t)row * DIMM + n0 + c) = v;
        }
        __syncthreads();
    }
}

// ---- kv partials: double-buffered cp.async, 8 rows per stage --------------
__global__ void __launch_bounds__(256)
kv_kernel(const float* __restrict__ K, const float* __restrict__ V,
          float* __restrict__ kvp, float* __restrict__ ksp) {
    const int bh = blockIdx.y;
    const int b = bh >> 4, h = bh & 15;
    const int chunk = blockIdx.x;
    const int t = threadIdx.x;

    __shared__ __align__(16) float ks[2][8][64];
    __shared__ __align__(16) float vs[2][8][64];

    const int td = (t >> 4) << 2;
    const int te = (t & 15) << 2;
    float acc[4][4] = {};
    float ksacc = 0.0f;

    const int nbase = chunk * (NN / KVC);   // 256 rows per chunk
    const int isv = t >> 7;                 // 0: K, 1: V
    const int lnn = (t >> 4) & 7;
    const int lc4 = (t & 15) * 4;
    const float* lsrc = (isv ? V : K);

    auto load_stage = [&](int it, int s) {
        const int n0 = nbase + it * 8;
        const float* src = lsrc + (size_t)(b * NN + n0 + lnn) * DIMM + h * HDD + lc4;
        float* dst = (isv ? &vs[s][lnn][lc4] : &ks[s][lnn][lc4]);
        cp_async16(dst, src);
    };

    load_stage(0, 0);
    asm volatile("cp.async.commit_group;\n");

    const int NIT = (NN / KVC) / 8;   // 32
    for (int it = 0; it < NIT; it++) {
        const int s = it & 1;
        asm volatile("cp.async.wait_group 0;\n");
        __syncthreads();
        if (it + 1 < NIT) {
            load_stage(it + 1, s ^ 1);
            asm volatile("cp.async.commit_group;\n");
        }
#pragma unroll
        for (int nn = 0; nn < 8; nn++) {
            float4 kd = *(const float4*)&ks[s][nn][td];
            float4 ve = *(const float4*)&vs[s][nn][te];
            acc[0][0] += kd.x * ve.x; acc[0][1] += kd.x * ve.y; acc[0][2] += kd.x * ve.z; acc[0][3] += kd.x * ve.w;
            acc[1][0] += kd.y * ve.x; acc[1][1] += kd.y * ve.y; acc[1][2] += kd.y * ve.z; acc[1][3] += kd.y * ve.w;
            acc[2][0] += kd.z * ve.x; acc[2][1] += kd.z * ve.y; acc[2][2] += kd.z * ve.z; acc[2][3] += kd.z * ve.w;
            acc[3][0] += kd.w * ve.x; acc[3][1] += kd.w * ve.y; acc[3][2] += kd.w * ve.z; acc[3][3] += kd.w * ve.w;
        }
        if (t < 64) {
#pragma unroll
            for (int nn = 0; nn < 8; nn++) ksacc += ks[s][nn][t];
        }
    }

    float* kvdst = kvp + ((size_t)chunk * 64 + bh) * (HDD * HDD);
#pragma unroll
    for (int i = 0; i < 4; i++)
#pragma unroll
        for (int j = 0; j < 4; j++)
            kvdst[(td + i) * HDD + te + j] = acc[i][j];
    if (t < 64) ksp[((size_t)chunk * 64 + bh) * HDD + t] = ksacc;
}

// ---- reduce partials ----
__global__ void __launch_bounds__(256)
reduce_kv(const float* __restrict__ kvp, const float* __restrict__ ksp,
          float* __restrict__ kv, float* __restrict__ ksum) {
    const int bh = blockIdx.x;
    const int t = threadIdx.x;
    for (int i = t; i < HDD * HDD; i += 256) {
        float s = 0.0f;
#pragma unroll
        for (int c = 0; c < KVC; c++)
            s += kvp[((size_t)c * 64 + bh) * (HDD * HDD) + i];
        kv[(size_t)bh * (HDD * HDD) + i] = s;
    }
    if (t < 64) {
        float s = 0.0f;
#pragma unroll
        for (int c = 0; c < KVC; c++)
            s += ksp[((size_t)c * 64 + bh) * HDD + t];
        ksum[bh * HDD + t] = s;
    }
}

// ---------------- out = (q.kv) / (q.ksum + eps) -------
__global__ void __launch_bounds__(256)
attn_kernel(const float* __restrict__ Q, const float* __restrict__ kv,
            const float* __restrict__ ksum, float* __restrict__ out) {
    const int bh = blockIdx.y;
    const int b = bh >> 4, h = bh & 15;
    const int t = threadIdx.x;
    const int w = t >> 5, l = t & 31;

    __shared__ float kvs[64 * 64];
    __shared__ float kss[64];
    __shared__ float qs[8][64];

    for (int i = t; i < 4096; i += 256) kvs[i] = kv[(size_t)bh * 4096 + i];
    if (t < 64) kss[t] = ksum[bh * 64 + t];
    __syncthreads();

    const int nbase = blockIdx.x * 128;
    for (int it = 0; it < 16; it++) {
        const int n = nbase + it * 8 + w;
        const float* qrow = Q + ((size_t)(b * NN + n)) * DIMM + h * HDD;
        float q0 = qrow[l];
        float q1 = qrow[l + 32];
        qs[w][l] = q0;
        qs[w][l + 32] = q1;
        __syncwarp();

        float p = q0 * kss[l] + q1 * kss[l + 32];
#pragma unroll
        for (int off = 16; off; off >>= 1) p += __shfl_xor_sync(0xffffffffu, p, off);
        const float denom = 1.0f / (p + 1e-6f);

        float a0 = 0.0f, a1 = 0.0f;
#pragma unroll 8
        for (int d = 0; d < 64; d++) {
            float qd = qs[w][d];
            a0 += qd * kvs[d * 64 + l];
            a1 += qd * kvs[d * 64 + l + 32];
        }
        float* orow = out + ((size_t)(b * NN + n)) * DIMM + h * HDD;
        orow[l] = a0 * denom;
        orow[l + 32] = a1 * denom;
        __syncwarp();
    }
}

// ---------------- launch ----------------
extern "C" void kernel_launch(void* const* d_in, const int* in_sizes, int n_in,
                              void* d_out, int out_size) {
    const float* query = (const float*)d_in[0];
    const float* key   = (const float*)d_in[1];
    const float* value = (const float*)d_in[2];
    const float* Wq = (const float*)d_in[3];
    const float* bq = (const float*)d_in[4];
    const float* Wk = (const float*)d_in[5];
    const float* bk = (const float*)d_in[6];
    const float* Wv = (const float*)d_in[7];
    const float* bv = (const float*)d_in[8];
    const float* Wo = (const float*)d_in[9];
    const float* bo = (const float*)d_in[10];
    const int* mask = (const int*)d_in[11];

    float *Qp, *Kp, *Vp, *Ap, *Wr, *KVPp, *KSPp, *KVp, *KSp;
    cudaGetSymbolAddress((void**)&Qp, g_Q);
    cudaGetSymbolAddress((void**)&Kp, g_K);
    cudaGetSymbolAddress((void**)&Vp, g_V);
    cudaGetSymbolAddress((void**)&Ap, g_A);
    cudaGetSymbolAddress((void**)&Wr, g_Wr);
    cudaGetSymbolAddress((void**)&KVPp, g_kvp);
    cudaGetSymbolAddress((void**)&KSPp, g_ksp);
    cudaGetSymbolAddress((void**)&KVp, g_kv);
    cudaGetSymbolAddress((void**)&KSp, g_ksum);

    dim3 ggrid(DIMM / 128, MM / 128);   // (8, 128)

    // 1: fused weight rounding
    round_w4<<<dim3(1024, 4), 256>>>(Wq, Wk, Wv, Wo, Wr);
    // 2, 3: K and V projections (kv depends on these)
    gemm_bias_act<<<ggrid, 256>>>(key,   Wr + 1 * (size_t)DIMM * DIMM, bk, mask,    Kp, 1);
    gemm_bias_act<<<ggrid, 256>>>(value, Wr + 2 * (size_t)DIMM * DIMM, bv, nullptr, Vp, 0);
    // 4: Q projection  <-- ncu profile slot
    gemm_bias_act<<<ggrid, 256>>>(query, Wr + 0 * (size_t)DIMM * DIMM, bq, nullptr, Qp, 1);
    // 5-7: attention chain
    kv_kernel<<<dim3(KVC, 64), 256>>>(Kp, Vp, KVPp, KSPp);
    reduce_kv<<<64, 256>>>(KVPp, KSPp, KVp, KSp);
    attn_kernel<<<dim3(32, 64), 256>>>(Qp, KVp, KSp, Ap);
    // 8: output projection
    gemm_bias_act<<<ggrid, 256>>>(Ap, Wr + 3 * (size_t)DIMM * DIMM, bo, nullptr, (float*)d_out, 0);
}

// round 10
// speedup vs baseline: 2.7703x; 2.3321x over previous
#include <cuda_runtime.h>
#include <cuda_fp16.h>
#include <mma.h>
#include <cstdint>

using namespace nvcuda;

// Problem constants
#define BB 4
#define NN 4096
#define DIMM 1024
#define HH 16
#define HDD 64
#define MM (BB * NN)           // 16384 rows
#define KVC 16                 // kv partial chunks

// ---------------- scratch (device globals; no allocation allowed) ----------
__device__ float  g_Q[(size_t)MM * DIMM];
__device__ float  g_K[(size_t)MM * DIMM];
__device__ float  g_V[(size_t)MM * DIMM];
__device__ __half g_hq[(size_t)MM * DIMM];    // fp16 query
__device__ __half g_hk[(size_t)MM * DIMM];    // fp16 key
__device__ __half g_hv[(size_t)MM * DIMM];    // fp16 value
__device__ __half g_hA[(size_t)MM * DIMM];    // fp16 attn output
__device__ __half g_Wh[4 * DIMM * DIMM];      // fp16 Wq,Wk,Wv,Wo
__device__ float  g_kvp[(size_t)KVC * BB * HH * HDD * HDD];
__device__ float  g_ksp[(size_t)KVC * BB * HH * HDD];
__device__ float  g_kv[BB * HH * HDD * HDD];
__device__ float  g_ksum[BB * HH * HDD];

__device__ __forceinline__ void cp_async16(void* smem_ptr, const void* gmem_ptr) {
    unsigned int s = (unsigned int)__cvta_generic_to_shared(smem_ptr);
    asm volatile("cp.async.cg.shared.global [%0], [%1], 16;\n" :: "r"(s), "l"(gmem_ptr));
}

// ---------------- fp32 -> fp16 conversion (RN) ----------------
__global__ void cvt_w4(const float* __restrict__ W0, const float* __restrict__ W1,
                       const float* __restrict__ W2, const float* __restrict__ W3,
                       __half* __restrict__ dst) {
    const float* srcs[4] = {W0, W1, W2, W3};
    const int m = blockIdx.y;
    const float4* s = (const float4*)srcs[m];
    __half2* d = (__half2*)(dst + (size_t)m * DIMM * DIMM);
    int i = blockIdx.x * blockDim.x + threadIdx.x;
    if (i < (DIMM * DIMM) / 4) {
        float4 v = s[i];
        d[2 * i + 0] = __floats2half2_rn(v.x, v.y);
        d[2 * i + 1] = __floats2half2_rn(v.z, v.w);
    }
}

__global__ void cvt_acts(const float* __restrict__ A0, const float* __restrict__ A1,
                         const float* __restrict__ A2, __half* __restrict__ D0,
                         __half* __restrict__ D1, __half* __restrict__ D2) {
    const float* srcs[3] = {A0, A1, A2};
    __half* dsts[3] = {D0, D1, D2};
    const int m = blockIdx.y;
    const float4* s = (const float4*)srcs[m];
    __half2* d = (__half2*)dsts[m];
    int i = blockIdx.x * blockDim.x + threadIdx.x;
    if (i < (MM * DIMM) / 4) {
        float4 v = s[i];
        d[2 * i + 0] = __floats2half2_rn(v.x, v.y);
        d[2 * i + 1] = __floats2half2_rn(v.z, v.w);
    }
}

// ---------------- fp16 GEMM: C[m,j] = act( A[m,:] . W[j,:] + bias[j] ) ----
// 128x128 block, K-chunk 32, 2-stage cp.async, 8 warps (32x64 warp tile).
#define KC 32
#define HPAD 40                            // halfs per row slice (32 + 8)
#define HTILE (128 * HPAD)                 // 5120 halfs
#define HSTAGE (2 * HTILE)                 // A + B = 10240 halfs

__global__ void __launch_bounds__(256, 2)
gemm_h(const __half* __restrict__ A, const __half* __restrict__ W,
       const float* __restrict__ bias, const int* __restrict__ mask,
       float* __restrict__ C, int do_relu) {
    __shared__ __align__(16) __half smem[2][HSTAGE];   // 40KB

    const int t = threadIdx.x;
    const int n0 = blockIdx.x * 128;
    const int m0 = blockIdx.y * 128;
    const int w = t >> 5;
    const int wm = w >> 1;   // 0..3 -> rows wm*32
    const int wn = w & 1;    // 0..1 -> cols wn*64

    wmma::fragment<wmma::accumulator, 16, 16, 16, float> acc[2][4];
#pragma unroll
    for (int i = 0; i < 2; i++)
#pragma unroll
        for (int j = 0; j < 4; j++)
            wmma::fill_fragment(acc[i][j], 0.0f);

    // per stage: A 128x32 halfs = 512 x 16B, B same. 2+2 chunks per thread.
    const int u0 = t;            // 0..255
    const int u1 = t + 256;      // 256..511
    const int r0 = u0 >> 2, c0 = (u0 & 3) * 8;
    const int r1 = u1 >> 2, c1 = (u1 & 3) * 8;

    const __half* Abase = A + (size_t)m0 * DIMM;
    const __half* Bbase = W + (size_t)n0 * DIMM;

    auto load_chunk = [&](int kc, int s) {
        __half* As = smem[s];
        __half* Bs = As + HTILE;
        const int k0 = kc * KC;
        cp_async16(&As[r0 * HPAD + c0], Abase + (size_t)r0 * DIMM + k0 + c0);
        cp_async16(&As[r1 * HPAD + c1], Abase + (size_t)r1 * DIMM + k0 + c1);
        cp_async16(&Bs[r0 * HPAD + c0], Bbase + (size_t)r0 * DIMM + k0 + c0);
        cp_async16(&Bs[r1 * HPAD + c1], Bbase + (size_t)r1 * DIMM + k0 + c1);
    };

    load_chunk(0, 0);
    asm volatile("cp.async.commit_group;\n");

    const int NCH = DIMM / KC;   // 32
    for (int i = 0; i < NCH; i++) {
        const int s = i & 1;
        if (i + 1 < NCH) {
            load_chunk(i + 1, s ^ 1);
            asm volatile("cp.async.commit_group;\n");
            asm volatile("cp.async.wait_group 1;\n");
        } else {
            asm volatile("cp.async.wait_group 0;\n");
        }
        __syncthreads();

        const __half* As = smem[s];
        const __half* Bs = As + HTILE;
#pragma unroll
        for (int kk = 0; kk < KC; kk += 16) {
            wmma::fragment<wmma::matrix_a, 16, 16, 16, __half, wmma::row_major> af[2];
            wmma::fragment<wmma::matrix_b, 16, 16, 16, __half, wmma::col_major> bf[4];
#pragma unroll
            for (int x = 0; x < 2; x++)
                wmma::load_matrix_sync(af[x], As + (wm * 32 + x * 16) * HPAD + kk, HPAD);
#pragma unroll
            for (int y = 0; y < 4; y++)
                wmma::load_matrix_sync(bf[y], Bs + (wn * 64 + y * 16) * HPAD + kk, HPAD);
#pragma unroll
            for (int x = 0; x < 2; x++)
#pragma unroll
                for (int y = 0; y < 4; y++)
                    wmma::mma_sync(acc[x][y], af[x], bf[y], acc[x][y]);
        }
        __syncthreads();
    }

    // ---- epilogue in two 64-row halves through smem (float, ldm 132) ----
    float* Ct = (float*)&smem[0][0];   // 64*132*4 = 33792B <= 40KB
#pragma unroll
    for (int half = 0; half < 2; half++) {
        if ((wm >> 1) == half) {
            const int wml = wm & 1;
#pragma unroll
            for (int x = 0; x < 2; x++)
#pragma unroll
                for (int y = 0; y < 4; y++)
                    wmma::store_matrix_sync(Ct + (wml * 32 + x * 16) * 132 + wn * 64 + y * 16,
                                            acc[x][y], 132, wmma::mem_row_major);
        }
        __syncthreads();
#pragma unroll
        for (int i = 0; i < 8; i++) {
            int u = t + i * 256;
            int r = u >> 5;
            int c = (u & 31) * 4;
            int row = m0 + half * 64 + r;
            float4 v = *(float4*)(Ct + r * 132 + c);
            v.x += bias[n0 + c + 0];
            v.y += bias[n0 + c + 1];
            v.z += bias[n0 + c + 2];
            v.w += bias[n0 + c + 3];
            if (do_relu) {
                v.x = fmaxf(v.x, 0.0f); v.y = fmaxf(v.y, 0.0f);
                v.z = fmaxf(v.z, 0.0f); v.w = fmaxf(v.w, 0.0f);
            }
            if (mask != nullptr && mask[row] != 0) {
                v.x = 0.0f; v.y = 0.0f; v.z = 0.0f; v.w = 0.0f;
            }
            *(float4*)(C + (size_t)row * DIMM + n0 + c) = v;
        }
        __syncthreads();
    }
}

// ---- kv partials: double-buffered cp.async, 8 rows per stage (fp32 in) ----
__global__ void __launch_bounds__(256)
kv_kernel(const float* __restrict__ K, const float* __restrict__ V,
          float* __restrict__ kvp, float* __restrict__ ksp) {
    const int bh = blockIdx.y;
    const int b = bh >> 4, h = bh & 15;
    const int chunk = blockIdx.x;
    const int t = threadIdx.x;

    __shared__ __align__(16) float ks[2][8][64];
    __shared__ __align__(16) float vs[2][8][64];

    const int td = (t >> 4) << 2;
    const int te = (t & 15) << 2;
    float acc[4][4] = {};
    float ksacc = 0.0f;

    const int nbase = chunk * (NN / KVC);   // 256 rows per chunk
    const int isv = t >> 7;
    const int lnn = (t >> 4) & 7;
    const int lc4 = (t & 15) * 4;
    const float* lsrc = (isv ? V : K);

    auto load_stage = [&](int it, int s) {
        const int n0 = nbase + it * 8;
        const float* src = lsrc + (size_t)(b * NN + n0 + lnn) * DIMM + h * HDD + lc4;
        float* dst = (isv ? &vs[s][lnn][lc4] : &ks[s][lnn][lc4]);
        cp_async16(dst, src);
    };

    load_stage(0, 0);
    asm volatile("cp.async.commit_group;\n");

    const int NIT = (NN / KVC) / 8;   // 32
    for (int it = 0; it < NIT; it++) {
        const int s = it & 1;
        asm volatile("cp.async.wait_group 0;\n");
        __syncthreads();
        if (it + 1 < NIT) {
            load_stage(it + 1, s ^ 1);
            asm volatile("cp.async.commit_group;\n");
        }
#pragma unroll
        for (int nn = 0; nn < 8; nn++) {
            float4 kd = *(const float4*)&ks[s][nn][td];
            float4 ve = *(const float4*)&vs[s][nn][te];
            acc[0][0] += kd.x * ve.x; acc[0][1] += kd.x * ve.y; acc[0][2] += kd.x * ve.z; acc[0][3] += kd.x * ve.w;
            acc[1][0] += kd.y * ve.x; acc[1][1] += kd.y * ve.y; acc[1][2] += kd.y * ve.z; acc[1][3] += kd.y * ve.w;
            acc[2][0] += kd.z * ve.x; acc[2][1] += kd.z * ve.y; acc[2][2] += kd.z * ve.z; acc[2][3] += kd.z * ve.w;
            acc[3][0] += kd.w * ve.x; acc[3][1] += kd.w * ve.y; acc[3][2] += kd.w * ve.z; acc[3][3] += kd.w * ve.w;
        }
        if (t < 64) {
#pragma unroll
            for (int nn = 0; nn < 8; nn++) ksacc += ks[s][nn][t];
        }
    }

    float* kvdst = kvp + ((size_t)chunk * 64 + bh) * (HDD * HDD);
#pragma unroll
    for (int i = 0; i < 4; i++)
#pragma unroll
        for (int j = 0; j < 4; j++)
            kvdst[(td + i) * HDD + te + j] = acc[i][j];
    if (t < 64) ksp[((size_t)chunk * 64 + bh) * HDD + t] = ksacc;
}

// ---- reduce partials ----
__global__ void __launch_bounds__(256)
reduce_kv(const float* __restrict__ kvp, const float* __restrict__ ksp,
          float* __restrict__ kv, float* __restrict__ ksum) {
    const int bh = blockIdx.x;
    const int t = threadIdx.x;
    for (int i = t; i < HDD * HDD; i += 256) {
        float s = 0.0f;
#pragma unroll
        for (int c = 0; c < KVC; c++)
            s += kvp[((size_t)c * 64 + bh) * (HDD * HDD) + i];
        kv[(size_t)bh * (HDD * HDD) + i] = s;
    }
    if (t < 64) {
        float s = 0.0f;
#pragma unroll
        for (int c = 0; c < KVC; c++)
            s += ksp[((size_t)c * 64 + bh) * HDD + t];
        ksum[bh * HDD + t] = s;
    }
}

// ---- out = (q.kv) / (q.ksum + eps), written as fp16 for the final GEMM ----
__global__ void __launch_bounds__(256)
attn_kernel(const float* __restrict__ Q, const float* __restrict__ kv,
            const float* __restrict__ ksum, __half* __restrict__ out) {
    const int bh = blockIdx.y;
    const int b = bh >> 4, h = bh & 15;
    const int t = threadIdx.x;
    const int w = t >> 5, l = t & 31;

    __shared__ float kvs[64 * 64];
    __shared__ float kss[64];
    __shared__ float qs[8][64];

    for (int i = t; i < 4096; i += 256) kvs[i] = kv[(size_t)bh * 4096 + i];
    if (t < 64) kss[t] = ksum[bh * 64 + t];
    __syncthreads();

    const int nbase = blockIdx.x * 128;
    for (int it = 0; it < 16; it++) {
        const int n = nbase + it * 8 + w;
        const float* qrow = Q + ((size_t)(b * NN + n)) * DIMM + h * HDD;
        float q0 = qrow[l];
        float q1 = qrow[l + 32];
        qs[w][l] = q0;
        qs[w][l + 32] = q1;
        __syncwarp();

        float p = q0 * kss[l] + q1 * kss[l + 32];
#pragma unroll
        for (int off = 16; off; off >>= 1) p += __shfl_xor_sync(0xffffffffu, p, off);
        const float denom = 1.0f / (p + 1e-6f);

        float a0 = 0.0f, a1 = 0.0f;
#pragma unroll 8
        for (int d = 0; d < 64; d++) {
            float qd = qs[w][d];
            a0 += qd * kvs[d * 64 + l];
            a1 += qd * kvs[d * 64 + l + 32];
        }
        __half* orow = out + ((size_t)(b * NN + n)) * DIMM + h * HDD;
        orow[l] = __float2half_rn(a0 * denom);
        orow[l + 32] = __float2half_rn(a1 * denom);
        __syncwarp();
    }
}

// ---------------- launch ----------------
extern "C" void kernel_launch(void* const* d_in, const int* in_sizes, int n_in,
                              void* d_out, int out_size) {
    const float* query = (const float*)d_in[0];
    const float* key   = (const float*)d_in[1];
    const float* value = (const float*)d_in[2];
    const float* Wq = (const float*)d_in[3];
    const float* bq = (const float*)d_in[4];
    const float* Wk = (const float*)d_in[5];
    const float* bk = (const float*)d_in[6];
    const float* Wv = (const float*)d_in[7];
    const float* bv = (const float*)d_in[8];
    const float* Wo = (const float*)d_in[9];
    const float* bo = (const float*)d_in[10];
    const int* mask = (const int*)d_in[11];

    float *Qp, *Kp, *Vp, *KVPp, *KSPp, *KVp, *KSp;
    __half *hq, *hk, *hv, *hA, *Wh;
    cudaGetSymbolAddress((void**)&Qp, g_Q);
    cudaGetSymbolAddress((void**)&Kp, g_K);
    cudaGetSymbolAddress((void**)&Vp, g_V);
    cudaGetSymbolAddress((void**)&hq, g_hq);
    cudaGetSymbolAddress((void**)&hk, g_hk);
    cudaGetSymbolAddress((void**)&hv, g_hv);
    cudaGetSymbolAddress((void**)&hA, g_hA);
    cudaGetSymbolAddress((void**)&Wh, g_Wh);
    cudaGetSymbolAddress((void**)&KVPp, g_kvp);
    cudaGetSymbolAddress((void**)&KSPp, g_ksp);
    cudaGetSymbolAddress((void**)&KVp, g_kv);
    cudaGetSymbolAddress((void**)&KSp, g_ksum);

    dim3 ggrid(DIMM / 128, MM / 128);   // (8, 128)

    // 1-2: fp16 conversion passes
    cvt_w4<<<dim3(1024, 4), 256>>>(Wq, Wk, Wv, Wo, Wh);
    cvt_acts<<<dim3(16384, 3), 256>>>(query, key, value, hq, hk, hv);
    // 3-4: K and V projections
    gemm_h<<<ggrid, 256>>>(hk, Wh + 1 * (size_t)DIMM * DIMM, bk, mask,    Kp, 1);
    gemm_h<<<ggrid, 256>>>(hv, Wh + 2 * (size_t)DIMM * DIMM, bv, nullptr, Vp, 0);
    // 5: kv reduction (needs only K, V)
    kv_kernel<<<dim3(KVC, 64), 256>>>(Kp, Vp, KVPp, KSPp);
    // 6: Q projection  <-- ncu profile slot
    gemm_h<<<ggrid, 256>>>(hq, Wh + 0 * (size_t)DIMM * DIMM, bq, nullptr, Qp, 1);
    // 7-8: reduce + attention
    reduce_kv<<<64, 256>>>(KVPp, KSPp, KVp, KSp);
    attn_kernel<<<dim3(32, 64), 256>>>(Qp, KVp, KSp, hA);
    // 9: output projection
    gemm_h<<<ggrid, 256>>>(hA, Wh + 3 * (size_t)DIMM * DIMM, bo, nullptr, (float*)d_out, 0);
}

// round 11
// speedup vs baseline: 2.9822x; 1.0765x over previous
#include <cuda_runtime.h>
#include <cuda_fp16.h>
#include <mma.h>
#include <cstdint>

using namespace nvcuda;

// Problem constants
#define BB 4
#define NN 4096
#define DIMM 1024
#define HH 16
#define HDD 64
#define MM (BB * NN)           // 16384 rows
#define KVC 16                 // kv partial chunks (256 rows each)

// ---------------- scratch (device globals; no allocation allowed) ----------
__device__ float  g_Q[(size_t)MM * DIMM];     // fp32 Q (attn input)
__device__ __half g_hq[(size_t)MM * DIMM];    // fp16 query (GEMM input)
__device__ __half g_hk[(size_t)MM * DIMM];    // fp16 key (GEMM input)
__device__ __half g_hv[(size_t)MM * DIMM];    // fp16 value (GEMM input)
__device__ __half g_K16[(size_t)MM * DIMM];   // fp16 K projection
__device__ __half g_V16[(size_t)MM * DIMM];   // fp16 V projection
__device__ __half g_hA[(size_t)MM * DIMM];    // fp16 attn output
__device__ __half g_Wh[4 * DIMM * DIMM];      // fp16 Wq,Wk,Wv,Wo
__device__ float  g_kvp[(size_t)KVC * BB * HH * HDD * HDD];
__device__ float  g_ksp[(size_t)KVC * BB * HH * HDD];
__device__ float  g_kv[BB * HH * HDD * HDD];
__device__ float  g_ksum[BB * HH * HDD];

__device__ __forceinline__ void cp_async16(void* smem_ptr, const void* gmem_ptr) {
    unsigned int s = (unsigned int)__cvta_generic_to_shared(smem_ptr);
    asm volatile("cp.async.cg.shared.global [%0], [%1], 16;\n" :: "r"(s), "l"(gmem_ptr));
}

// ---------------- fp32 -> fp16 conversion (RN) ----------------
__global__ void cvt_w4(const float* __restrict__ W0, const float* __restrict__ W1,
                       const float* __restrict__ W2, const float* __restrict__ W3,
                       __half* __restrict__ dst) {
    const float* srcs[4] = {W0, W1, W2, W3};
    const int m = blockIdx.y;
    const float4* s = (const float4*)srcs[m];
    __half2* d = (__half2*)(dst + (size_t)m * DIMM * DIMM);
    int i = blockIdx.x * blockDim.x + threadIdx.x;
    if (i < (DIMM * DIMM) / 4) {
        float4 v = s[i];
        d[2 * i + 0] = __floats2half2_rn(v.x, v.y);
        d[2 * i + 1] = __floats2half2_rn(v.z, v.w);
    }
}

__global__ void cvt_acts(const float* __restrict__ A0, const float* __restrict__ A1,
                         const float* __restrict__ A2, __half* __restrict__ D0,
                         __half* __restrict__ D1, __half* __restrict__ D2) {
    const float* srcs[3] = {A0, A1, A2};
    __half* dsts[3] = {D0, D1, D2};
    const int m = blockIdx.y;
    const float4* s = (const float4*)srcs[m];
    __half2* d = (__half2*)dsts[m];
    int i = blockIdx.x * blockDim.x + threadIdx.x;
    if (i < (MM * DIMM) / 4) {
        float4 v = s[i];
        d[2 * i + 0] = __floats2half2_rn(v.x, v.y);
        d[2 * i + 1] = __floats2half2_rn(v.z, v.w);
    }
}

// ---------------- fp16 GEMM: 128x128 block, K-chunk 32, 3-stage -----------
// Writes EITHER fp32 (Cf) or fp16 (Ch) output.
#define KC 32
#define HPAD 40                            // halfs per row slice (32 + 8)
#define HTILE (128 * HPAD)                 // 5120 halfs
#define HSTAGE (2 * HTILE)                 // A + B = 10240 halfs
#define GSTG 3
#define GEMM_DSMEM (GSTG * HSTAGE * 2)     // 61440 bytes

extern __shared__ __align__(16) __half dsm_h[];

__global__ void __launch_bounds__(256, 2)
gemm_h(const __half* __restrict__ A, const __half* __restrict__ W,
       const float* __restrict__ bias, const int* __restrict__ mask,
       float* __restrict__ Cf, __half* __restrict__ Ch, int do_relu) {
    const int t = threadIdx.x;
    const int n0 = blockIdx.x * 128;
    const int m0 = blockIdx.y * 128;
    const int w = t >> 5;
    const int wm = w >> 1;   // 0..3 -> rows wm*32
    const int wn = w & 1;    // 0..1 -> cols wn*64

    wmma::fragment<wmma::accumulator, 16, 16, 16, float> acc[2][4];
#pragma unroll
    for (int i = 0; i < 2; i++)
#pragma unroll
        for (int j = 0; j < 4; j++)
            wmma::fill_fragment(acc[i][j], 0.0f);

    const int u0 = t;            // 0..255
    const int u1 = t + 256;      // 256..511
    const int r0 = u0 >> 2, c0 = (u0 & 3) * 8;
    const int r1 = u1 >> 2, c1 = (u1 & 3) * 8;

    const __half* Abase = A + (size_t)m0 * DIMM;
    const __half* Bbase = W + (size_t)n0 * DIMM;

    auto load_chunk = [&](int kc, int s) {
        __half* As = dsm_h + s * HSTAGE;
        __half* Bs = As + HTILE;
        const int k0 = kc * KC;
        cp_async16(&As[r0 * HPAD + c0], Abase + (size_t)r0 * DIMM + k0 + c0);
        cp_async16(&As[r1 * HPAD + c1], Abase + (size_t)r1 * DIMM + k0 + c1);
        cp_async16(&Bs[r0 * HPAD + c0], Bbase + (size_t)r0 * DIMM + k0 + c0);
        cp_async16(&Bs[r1 * HPAD + c1], Bbase + (size_t)r1 * DIMM + k0 + c1);
    };

    load_chunk(0, 0);
    asm volatile("cp.async.commit_group;\n");
    load_chunk(1, 1);
    asm volatile("cp.async.commit_group;\n");

    const int NCH = DIMM / KC;   // 32
    for (int i = 0; i < NCH; i++) {
        const int s = i % GSTG;
        asm volatile("cp.async.wait_group 1;\n");
        __syncthreads();
        if (i + 2 < NCH) {
            load_chunk(i + 2, (i + 2) % GSTG);
            asm volatile("cp.async.commit_group;\n");
        }

        const __half* As = dsm_h + s * HSTAGE;
        const __half* Bs = As + HTILE;
#pragma unroll
        for (int kk = 0; kk < KC; kk += 16) {
            wmma::fragment<wmma::matrix_a, 16, 16, 16, __half, wmma::row_major> af[2];
            wmma::fragment<wmma::matrix_b, 16, 16, 16, __half, wmma::col_major> bf[4];
#pragma unroll
            for (int x = 0; x < 2; x++)
                wmma::load_matrix_sync(af[x], As + (wm * 32 + x * 16) * HPAD + kk, HPAD);
#pragma unroll
            for (int y = 0; y < 4; y++)
                wmma::load_matrix_sync(bf[y], Bs + (wn * 64 + y * 16) * HPAD + kk, HPAD);
#pragma unroll
            for (int x = 0; x < 2; x++)
#pragma unroll
                for (int y = 0; y < 4; y++)
                    wmma::mma_sync(acc[x][y], af[x], bf[y], acc[x][y]);
        }
        __syncthreads();
    }

    // ---- epilogue in two 64-row halves through smem (float, ldm 132) ----
    float* Ct = (float*)dsm_h;   // 64*132*4 = 33792B <= 61440B
#pragma unroll
    for (int half = 0; half < 2; half++) {
        if ((wm >> 1) == half) {
            const int wml = wm & 1;
#pragma unroll
            for (int x = 0; x < 2; x++)
#pragma unroll
                for (int y = 0; y < 4; y++)
                    wmma::store_matrix_sync(Ct + (wml * 32 + x * 16) * 132 + wn * 64 + y * 16,
                                            acc[x][y], 132, wmma::mem_row_major);
        }
        __syncthreads();
#pragma unroll
        for (int i = 0; i < 8; i++) {
            int u = t + i * 256;
            int r = u >> 5;
            int c = (u & 31) * 4;
            int row = m0 + half * 64 + r;
            float4 v = *(float4*)(Ct + r * 132 + c);
            v.x += bias[n0 + c + 0];
            v.y += bias[n0 + c + 1];
            v.z += bias[n0 + c + 2];
            v.w += bias[n0 + c + 3];
            if (do_relu) {
                v.x = fmaxf(v.x, 0.0f); v.y = fmaxf(v.y, 0.0f);
                v.z = fmaxf(v.z, 0.0f); v.w = fmaxf(v.w, 0.0f);
            }
            if (mask != nullptr && mask[row] != 0) {
                v.x = 0.0f; v.y = 0.0f; v.z = 0.0f; v.w = 0.0f;
            }
            if (Ch != nullptr) {
                __half2* p = (__half2*)(Ch + (size_t)row * DIMM + n0 + c);
                p[0] = __floats2half2_rn(v.x, v.y);
                p[1] = __floats2half2_rn(v.z, v.w);
            } else {
                *(float4*)(Cf + (size_t)row * DIMM + n0 + c) = v;
            }
        }
        __syncthreads();
    }
}

// ---- kv partials via fp16 WMMA: kvp[c][bh] = K_c^T @ V_c (64x64x256) -----
#define KVPAD 72
__global__ void __launch_bounds__(128)
kv_h(const __half* __restrict__ K, const __half* __restrict__ V,
     float* __restrict__ kvp, float* __restrict__ ksp) {
    __shared__ __align__(16) __half Ks[128][KVPAD];
    __shared__ __align__(16) __half Vs[128][KVPAD];
    __shared__ float ksb[128];

    const int bh = blockIdx.y;
    const int b = bh >> 4, h = bh & 15;
    const int chunk = blockIdx.x;
    const int t = threadIdx.x;
    const int w = t >> 5;
    const int d0 = w * 16;
    const int dcol = t & 63, rhalf = t >> 6;

    wmma::fragment<wmma::accumulator, 16, 16, 16, float> acc[4];
#pragma unroll
    for (int e = 0; e < 4; e++) wmma::fill_fragment(acc[e], 0.0f);
    float ksacc = 0.0f;

#pragma unroll
    for (int sub = 0; sub < 2; sub++) {
        const int n0 = chunk * 256 + sub * 128;
        // load 128 rows x 64 halfs of K and V
#pragma unroll
        for (int j = 0; j < 8; j++) {
            int u = t + j * 128;
            int row = u >> 3;
            int c8 = (u & 7) * 8;
            const size_t goff = (size_t)(b * NN + n0 + row) * DIMM + h * HDD + c8;
            cp_async16(&Ks[row][c8], K + goff);
            cp_async16(&Vs[row][c8], V + goff);
        }
        asm volatile("cp.async.commit_group;\n");
        asm volatile("cp.async.wait_group 0;\n");
        __syncthreads();

        // ksum partial: thread t sums col (t&63) over rows [rhalf*64, +64)
#pragma unroll 16
        for (int r = rhalf * 64; r < rhalf * 64 + 64; r++)
            ksacc += __half2float(Ks[r][dcol]);

        // kv: A = K^T (col-major view of Ks), B = V (row-major)
#pragma unroll
        for (int ns = 0; ns < 128; ns += 16) {
            wmma::fragment<wmma::matrix_a, 16, 16, 16, __half, wmma::col_major> a;
            wmma::load_matrix_sync(a, &Ks[ns][d0], KVPAD);
#pragma unroll
            for (int e = 0; e < 4; e++) {
                wmma::fragment<wmma::matrix_b, 16, 16, 16, __half, wmma::row_major> bfr;
                wmma::load_matrix_sync(bfr, &Vs[ns][e * 16], KVPAD);
                wmma::mma_sync(acc[e], a, bfr, acc[e]);
            }
        }
        __syncthreads();
    }

    float* dst = kvp + ((size_t)chunk * 64 + bh) * (HDD * HDD);
#pragma unroll
    for (int e = 0; e < 4; e++)
        wmma::store_matrix_sync(dst + d0 * 64 + e * 16, acc[e], 64, wmma::mem_row_major);

    ksb[t] = ksacc;
    __syncthreads();
    if (t < 64) ksp[((size_t)chunk * 64 + bh) * HDD + t] = ksb[t] + ksb[t + 64];
}

// ---- reduce partials ----
__global__ void __launch_bounds__(256)
reduce_kv(const float* __restrict__ kvp, const float* __restrict__ ksp,
          float* __restrict__ kv, float* __restrict__ ksum) {
    const int bh = blockIdx.x;
    const int t = threadIdx.x;
    for (int i = t; i < HDD * HDD; i += 256) {
        float s = 0.0f;
#pragma unroll
        for (int c = 0; c < KVC; c++)
            s += kvp[((size_t)c * 64 + bh) * (HDD * HDD) + i];
        kv[(size_t)bh * (HDD * HDD) + i] = s;
    }
    if (t < 64) {
        float s = 0.0f;
#pragma unroll
        for (int c = 0; c < KVC; c++)
            s += ksp[((size_t)c * 64 + bh) * HDD + t];
        ksum[bh * HDD + t] = s;
    }
}

// ---- out = (q.kv) / (q.ksum + eps), written as fp16 for the final GEMM ----
__global__ void __launch_bounds__(256)
attn_kernel(const float* __restrict__ Q, const float* __restrict__ kv,
            const float* __restrict__ ksum, __half* __restrict__ out) {
    const int bh = blockIdx.y;
    const int b = bh >> 4, h = bh & 15;
    const int t = threadIdx.x;
    const int w = t >> 5, l = t & 31;

    __shared__ float kvs[64 * 64];
    __shared__ float kss[64];
    __shared__ float qs[8][64];

    for (int i = t; i < 4096; i += 256) kvs[i] = kv[(size_t)bh * 4096 + i];
    if (t < 64) kss[t] = ksum[bh * 64 + t];
    __syncthreads();

    const int nbase = blockIdx.x * 128;
    for (int it = 0; it < 16; it++) {
        const int n = nbase + it * 8 + w;
        const float* qrow = Q + ((size_t)(b * NN + n)) * DIMM + h * HDD;
        float q0 = qrow[l];
        float q1 = qrow[l + 32];
        qs[w][l] = q0;
        qs[w][l + 32] = q1;
        __syncwarp();

        float p = q0 * kss[l] + q1 * kss[l + 32];
#pragma unroll
        for (int off = 16; off; off >>= 1) p += __shfl_xor_sync(0xffffffffu, p, off);
        const float denom = 1.0f / (p + 1e-6f);

        float a0 = 0.0f, a1 = 0.0f;
#pragma unroll 8
        for (int d = 0; d < 64; d++) {
            float qd = qs[w][d];
            a0 += qd * kvs[d * 64 + l];
            a1 += qd * kvs[d * 64 + l + 32];
        }
        __half* orow = out + ((size_t)(b * NN + n)) * DIMM + h * HDD;
        orow[l] = __float2half_rn(a0 * denom);
        orow[l + 32] = __float2half_rn(a1 * denom);
        __syncwarp();
    }
}

// ---------------- launch ----------------
extern "C" void kernel_launch(void* const* d_in, const int* in_sizes, int n_in,
                              void* d_out, int out_size) {
    const float* query = (const float*)d_in[0];
    const float* key   = (const float*)d_in[1];
    const float* value = (const float*)d_in[2];
    const float* Wq = (const float*)d_in[3];
    const float* bq = (const float*)d_in[4];
    const float* Wk = (const float*)d_in[5];
    const float* bk = (const float*)d_in[6];
    const float* Wv = (const float*)d_in[7];
    const float* bv = (const float*)d_in[8];
    const float* Wo = (const float*)d_in[9];
    const float* bo = (const float*)d_in[10];
    const int* mask = (const int*)d_in[11];

    float *Qp, *KVPp, *KSPp, *KVp, *KSp;
    __half *hq, *hk, *hv, *K16, *V16, *hA, *Wh;
    cudaGetSymbolAddress((void**)&Qp, g_Q);
    cudaGetSymbolAddress((void**)&hq, g_hq);
    cudaGetSymbolAddress((void**)&hk, g_hk);
    cudaGetSymbolAddress((void**)&hv, g_hv);
    cudaGetSymbolAddress((void**)&K16, g_K16);
    cudaGetSymbolAddress((void**)&V16, g_V16);
    cudaGetSymbolAddress((void**)&hA, g_hA);
    cudaGetSymbolAddress((void**)&Wh, g_Wh);
    cudaGetSymbolAddress((void**)&KVPp, g_kvp);
    cudaGetSymbolAddress((void**)&KSPp, g_ksp);
    cudaGetSymbolAddress((void**)&KVp, g_kv);
    cudaGetSymbolAddress((void**)&KSp, g_ksum);

    cudaFuncSetAttribute(gemm_h, cudaFuncAttributeMaxDynamicSharedMemorySize, GEMM_DSMEM);

    dim3 ggrid(DIMM / 128, MM / 128);   // (8, 128)

    // 1-2: fp16 conversion passes
    cvt_w4<<<dim3(1024, 4), 256>>>(Wq, Wk, Wv, Wo, Wh);
    cvt_acts<<<dim3(16384, 3), 256>>>(query, key, value, hq, hk, hv);
    // 3-4: K and V projections (fp16 out)
    gemm_h<<<ggrid, 256, GEMM_DSMEM>>>(hk, Wh + 1 * (size_t)DIMM * DIMM, bk, mask,    nullptr, K16, 1);
    gemm_h<<<ggrid, 256, GEMM_DSMEM>>>(hv, Wh + 2 * (size_t)DIMM * DIMM, bv, nullptr, nullptr, V16, 0);
    // 5: kv reduction (fp16 WMMA)
    kv_h<<<dim3(KVC, 64), 128>>>(K16, V16, KVPp, KSPp);
    // 6: Q projection (fp32 out)  <-- ncu profile slot
    gemm_h<<<ggrid, 256, GEMM_DSMEM>>>(hq, Wh + 0 * (size_t)DIMM * DIMM, bq, nullptr, Qp, nullptr, 1);
    // 7-8: reduce + attention
    reduce_kv<<<64, 256>>>(KVPp, KSPp, KVp, KSp);
    attn_kernel<<<dim3(32, 64), 256>>>(Qp, KVp, KSp, hA);
    // 9: output projection (fp32 out to d_out)
    gemm_h<<<ggrid, 256, GEMM_DSMEM>>>(hA, Wh + 3 * (size_t)DIMM * DIMM, bo, nullptr, (float*)d_out, nullptr, 0);
}

// round 12
// speedup vs baseline: 3.2865x; 1.1020x over previous
#include <cuda_runtime.h>
#include <cuda_fp16.h>
#include <mma.h>
#include <cstdint>

using namespace nvcuda;

// Problem constants
#define BB 4
#define NN 4096
#define DIMM 1024
#define HH 16
#define HDD 64
#define MM (BB * NN)           // 16384 rows
#define KVC 16                 // kv partial chunks (256 rows each)

// ---------------- scratch (device globals; no allocation allowed) ----------
__device__ __half g_hq[(size_t)MM * DIMM];    // fp16 query (GEMM input)
__device__ __half g_hk[(size_t)MM * DIMM];    // fp16 key (GEMM input)
__device__ __half g_hv[(size_t)MM * DIMM];    // fp16 value (GEMM input)
__device__ __half g_Q16[(size_t)MM * DIMM];   // fp16 Q projection
__device__ __half g_K16[(size_t)MM * DIMM];   // fp16 K projection
__device__ __half g_V16[(size_t)MM * DIMM];   // fp16 V projection
__device__ __half g_hA[(size_t)MM * DIMM];    // fp16 attn output
__device__ __half g_Wh[4 * DIMM * DIMM];      // fp16 Wq,Wk,Wv,Wo
__device__ float  g_kvp[(size_t)KVC * BB * HH * HDD * HDD];
__device__ float  g_ksp[(size_t)KVC * BB * HH * HDD];
__device__ float  g_kv[BB * HH * HDD * HDD];
__device__ float  g_ksum[BB * HH * HDD];

__device__ __forceinline__ void cp_async16(void* smem_ptr, const void* gmem_ptr) {
    unsigned int s = (unsigned int)__cvta_generic_to_shared(smem_ptr);
    asm volatile("cp.async.cg.shared.global [%0], [%1], 16;\n" :: "r"(s), "l"(gmem_ptr));
}

// ---------------- fp32 -> fp16 conversion (RN) ----------------
__global__ void cvt_w4(const float* __restrict__ W0, const float* __restrict__ W1,
                       const float* __restrict__ W2, const float* __restrict__ W3,
                       __half* __restrict__ dst) {
    const float* srcs[4] = {W0, W1, W2, W3};
    const int m = blockIdx.y;
    const float4* s = (const float4*)srcs[m];
    __half2* d = (__half2*)(dst + (size_t)m * DIMM * DIMM);
    int i = blockIdx.x * blockDim.x + threadIdx.x;
    if (i < (DIMM * DIMM) / 4) {
        float4 v = s[i];
        d[2 * i + 0] = __floats2half2_rn(v.x, v.y);
        d[2 * i + 1] = __floats2half2_rn(v.z, v.w);
    }
}

__global__ void cvt_acts(const float* __restrict__ A0, const float* __restrict__ A1,
                         const float* __restrict__ A2, __half* __restrict__ D0,
                         __half* __restrict__ D1, __half* __restrict__ D2) {
    const float* srcs[3] = {A0, A1, A2};
    __half* dsts[3] = {D0, D1, D2};
    const int m = blockIdx.y;
    const float4* s = (const float4*)srcs[m];
    __half2* d = (__half2*)dsts[m];
    int i = blockIdx.x * blockDim.x + threadIdx.x;
    if (i < (MM * DIMM) / 4) {
        float4 v = s[i];
        d[2 * i + 0] = __floats2half2_rn(v.x, v.y);
        d[2 * i + 1] = __floats2half2_rn(v.z, v.w);
    }
}

// ============ fp16 GEMM core: 128x128 block, K-chunk 64, 2-stage ==========
#define KC 64
#define HPAD 72                            // halfs per row slice (64 + 8)
#define HTILE (128 * HPAD)                 // 9216 halfs
#define HSTAGE (2 * HTILE)                 // A + B = 18432 halfs
#define GEMM_DSMEM (2 * HSTAGE * 2)        // 73728 bytes

extern __shared__ __align__(16) __half dsm_h[];

struct GemmCore {
    wmma::fragment<wmma::accumulator, 16, 16, 16, float> acc[2][4];
    int t, w, wm, wn, r0, c0, r1, c1;

    __device__ __forceinline__ void init(int tid) {
        t = tid; w = t >> 5; wm = w >> 1; wn = w & 1;
#pragma unroll
        for (int i = 0; i < 2; i++)
#pragma unroll
            for (int j = 0; j < 4; j++)
                wmma::fill_fragment(acc[i][j], 0.0f);
    }

    __device__ __forceinline__ void load_chunk(const __half* Abase, const __half* Bbase,
                                               int kc, int s) {
        __half* As = dsm_h + s * HSTAGE;
        __half* Bs = As + HTILE;
        const int k0 = kc * KC;
#pragma unroll
        for (int j = 0; j < 4; j++) {
            int u = t + j * 256;
            int row = u >> 3;
            int c8 = (u & 7) * 8;
            cp_async16(&As[row * HPAD + c8], Abase + (size_t)row * DIMM + k0 + c8);
            cp_async16(&Bs[row * HPAD + c8], Bbase + (size_t)row * DIMM + k0 + c8);
        }
    }

    __device__ __forceinline__ void mainloop(const __half* Abase, const __half* Bbase) {
        load_chunk(Abase, Bbase, 0, 0);
        asm volatile("cp.async.commit_group;\n");
        const int NCH = DIMM / KC;   // 16
        for (int i = 0; i < NCH; i++) {
            const int s = i & 1;
            if (i + 1 < NCH) {
                load_chunk(Abase, Bbase, i + 1, s ^ 1);
                asm volatile("cp.async.commit_group;\n");
                asm volatile("cp.async.wait_group 1;\n");
            } else {
                asm volatile("cp.async.wait_group 0;\n");
            }
            __syncthreads();

            const __half* As = dsm_h + s * HSTAGE;
            const __half* Bs = As + HTILE;
#pragma unroll
            for (int kk = 0; kk < KC; kk += 16) {
                wmma::fragment<wmma::matrix_a, 16, 16, 16, __half, wmma::row_major> af[2];
                wmma::fragment<wmma::matrix_b, 16, 16, 16, __half, wmma::col_major> bf[4];
#pragma unroll
                for (int x = 0; x < 2; x++)
                    wmma::load_matrix_sync(af[x], As + (wm * 32 + x * 16) * HPAD + kk, HPAD);
#pragma unroll
                for (int y = 0; y < 4; y++)
                    wmma::load_matrix_sync(bf[y], Bs + (wn * 64 + y * 16) * HPAD + kk, HPAD);
#pragma unroll
                for (int x = 0; x < 2; x++)
#pragma unroll
                    for (int y = 0; y < 4; y++)
                        wmma::mma_sync(acc[x][y], af[x], bf[y], acc[x][y]);
            }
            __syncthreads();
        }
    }

    // epilogue: bias+act+mask; writes fp16 (Ch) or fp32 (Cf)
    __device__ __forceinline__ void epilogue(const float* bias, const int* mask,
                                             float* Cf, __half* Ch, int do_relu,
                                             int m0, int n0) {
        float* Ct = (float*)dsm_h;
#pragma unroll
        for (int half = 0; half < 2; half++) {
            if ((wm >> 1) == half) {
                const int wml = wm & 1;
#pragma unroll
                for (int x = 0; x < 2; x++)
#pragma unroll
                    for (int y = 0; y < 4; y++)
                        wmma::store_matrix_sync(Ct + (wml * 32 + x * 16) * 132 + wn * 64 + y * 16,
                                                acc[x][y], 132, wmma::mem_row_major);
            }
            __syncthreads();
#pragma unroll
            for (int i = 0; i < 8; i++) {
                int u = t + i * 256;
                int r = u >> 5;
                int c = (u & 31) * 4;
                int row = m0 + half * 64 + r;
                float4 v = *(float4*)(Ct + r * 132 + c);
                v.x += bias[n0 + c + 0];
                v.y += bias[n0 + c + 1];
                v.z += bias[n0 + c + 2];
                v.w += bias[n0 + c + 3];
                if (do_relu) {
                    v.x = fmaxf(v.x, 0.0f); v.y = fmaxf(v.y, 0.0f);
                    v.z = fmaxf(v.z, 0.0f); v.w = fmaxf(v.w, 0.0f);
                }
                if (mask != nullptr && mask[row] != 0) {
                    v.x = 0.0f; v.y = 0.0f; v.z = 0.0f; v.w = 0.0f;
                }
                if (Ch != nullptr) {
                    __half2* p = (__half2*)(Ch + (size_t)row * DIMM + n0 + c);
                    p[0] = __floats2half2_rn(v.x, v.y);
                    p[1] = __floats2half2_rn(v.z, v.w);
                } else {
                    *(float4*)(Cf + (size_t)row * DIMM + n0 + c) = v;
                }
            }
            __syncthreads();
        }
    }
};

// merged Q/K/V projection: blockIdx.z selects matrix
__global__ void __launch_bounds__(256, 2)
gemm_qkv(const __half* __restrict__ hq, const __half* __restrict__ hk,
         const __half* __restrict__ hv, const __half* __restrict__ Wh,
         const float* __restrict__ bq, const float* __restrict__ bk,
         const float* __restrict__ bv, const int* __restrict__ mask,
         __half* __restrict__ Q16, __half* __restrict__ K16, __half* __restrict__ V16) {
    const int z = blockIdx.z;
    const __half* A = (z == 0) ? hq : (z == 1) ? hk : hv;
    const __half* W = Wh + (size_t)z * DIMM * DIMM;
    const float* bias = (z == 0) ? bq : (z == 1) ? bk : bv;
    const int* mk = (z == 1) ? mask : nullptr;
    __half* out = (z == 0) ? Q16 : (z == 1) ? K16 : V16;
    const int do_relu = (z < 2);

    GemmCore g;
    g.init(threadIdx.x);
    const int n0 = blockIdx.x * 128;
    const int m0 = blockIdx.y * 128;
    g.mainloop(A + (size_t)m0 * DIMM, W + (size_t)n0 * DIMM);
    g.epilogue(bias, mk, nullptr, out, do_relu, m0, n0);
}

// single GEMM (final projection, fp32 out)
__global__ void __launch_bounds__(256, 2)
gemm_one(const __half* __restrict__ A, const __half* __restrict__ W,
         const float* __restrict__ bias, float* __restrict__ Cf) {
    GemmCore g;
    g.init(threadIdx.x);
    const int n0 = blockIdx.x * 128;
    const int m0 = blockIdx.y * 128;
    g.mainloop(A + (size_t)m0 * DIMM, W + (size_t)n0 * DIMM);
    g.epilogue(bias, nullptr, Cf, nullptr, 0, m0, n0);
}

// ---- kv partials via fp16 WMMA: kvp[c][bh] = K_c^T @ V_c (64x64x256) -----
#define KVPAD 72
__global__ void __launch_bounds__(128)
kv_h(const __half* __restrict__ K, const __half* __restrict__ V,
     float* __restrict__ kvp, float* __restrict__ ksp) {
    __shared__ __align__(16) __half Ks[128][KVPAD];
    __shared__ __align__(16) __half Vs[128][KVPAD];
    __shared__ float ksb[128];

    const int bh = blockIdx.y;
    const int b = bh >> 4, h = bh & 15;
    const int chunk = blockIdx.x;
    const int t = threadIdx.x;
    const int w = t >> 5;
    const int d0 = w * 16;
    const int dcol = t & 63, rhalf = t >> 6;

    wmma::fragment<wmma::accumulator, 16, 16, 16, float> acc[4];
#pragma unroll
    for (int e = 0; e < 4; e++) wmma::fill_fragment(acc[e], 0.0f);
    float ksacc = 0.0f;

#pragma unroll
    for (int sub = 0; sub < 2; sub++) {
        const int n0 = chunk * 256 + sub * 128;
#pragma unroll
        for (int j = 0; j < 8; j++) {
            int u = t + j * 128;
            int row = u >> 3;
            int c8 = (u & 7) * 8;
            const size_t goff = (size_t)(b * NN + n0 + row) * DIMM + h * HDD + c8;
            cp_async16(&Ks[row][c8], K + goff);
            cp_async16(&Vs[row][c8], V + goff);
        }
        asm volatile("cp.async.commit_group;\n");
        asm volatile("cp.async.wait_group 0;\n");
        __syncthreads();

#pragma unroll 16
        for (int r = rhalf * 64; r < rhalf * 64 + 64; r++)
            ksacc += __half2float(Ks[r][dcol]);

#pragma unroll
        for (int ns = 0; ns < 128; ns += 16) {
            wmma::fragment<wmma::matrix_a, 16, 16, 16, __half, wmma::col_major> a;
            wmma::load_matrix_sync(a, &Ks[ns][d0], KVPAD);
#pragma unroll
            for (int e = 0; e < 4; e++) {
                wmma::fragment<wmma::matrix_b, 16, 16, 16, __half, wmma::row_major> bfr;
                wmma::load_matrix_sync(bfr, &Vs[ns][e * 16], KVPAD);
                wmma::mma_sync(acc[e], a, bfr, acc[e]);
            }
        }
        __syncthreads();
    }

    float* dst = kvp + ((size_t)chunk * 64 + bh) * (HDD * HDD);
#pragma unroll
    for (int e = 0; e < 4; e++)
        wmma::store_matrix_sync(dst + d0 * 64 + e * 16, acc[e], 64, wmma::mem_row_major);

    ksb[t] = ksacc;
    __syncthreads();
    if (t < 64) ksp[((size_t)chunk * 64 + bh) * HDD + t] = ksb[t] + ksb[t + 64];
}

// ---- reduce partials ----
__global__ void __launch_bounds__(256)
reduce_kv(const float* __restrict__ kvp, const float* __restrict__ ksp,
          float* __restrict__ kv, float* __restrict__ ksum) {
    const int bh = blockIdx.x;
    const int t = threadIdx.x;
    for (int i = t; i < HDD * HDD; i += 256) {
        float s = 0.0f;
#pragma unroll
        for (int c = 0; c < KVC; c++)
            s += kvp[((size_t)c * 64 + bh) * (HDD * HDD) + i];
        kv[(size_t)bh * (HDD * HDD) + i] = s;
    }
    if (t < 64) {
        float s = 0.0f;
#pragma unroll
        for (int c = 0; c < KVC; c++)
            s += ksp[((size_t)c * 64 + bh) * HDD + t];
        ksum[bh * HDD + t] = s;
    }
}

// ---- out = (q.kv) / (q.ksum + eps); fp16 in, fp16 out ----
__global__ void __launch_bounds__(256)
attn_kernel(const __half* __restrict__ Q, const float* __restrict__ kv,
            const float* __restrict__ ksum, __half* __restrict__ out) {
    const int bh = blockIdx.y;
    const int b = bh >> 4, h = bh & 15;
    const int t = threadIdx.x;
    const int w = t >> 5, l = t & 31;

    __shared__ float kvs[64 * 64];
    __shared__ float kss[64];
    __shared__ float qs[8][64];

    for (int i = t; i < 4096; i += 256) kvs[i] = kv[(size_t)bh * 4096 + i];
    if (t < 64) kss[t] = ksum[bh * 64 + t];
    __syncthreads();

    const int nbase = blockIdx.x * 128;
    for (int it = 0; it < 16; it++) {
        const int n = nbase + it * 8 + w;
        const __half* qrow = Q + ((size_t)(b * NN + n)) * DIMM + h * HDD;
        float q0 = __half2float(qrow[l]);
        float q1 = __half2float(qrow[l + 32]);
        qs[w][l] = q0;
        qs[w][l + 32] = q1;
        __syncwarp();

        float p = q0 * kss[l] + q1 * kss[l + 32];
#pragma unroll
        for (int off = 16; off; off >>= 1) p += __shfl_xor_sync(0xffffffffu, p, off);
        const float denom = 1.0f / (p + 1e-6f);

        float a0 = 0.0f, a1 = 0.0f;
#pragma unroll 8
        for (int d = 0; d < 64; d++) {
            float qd = qs[w][d];
            a0 += qd * kvs[d * 64 + l];
            a1 += qd * kvs[d * 64 + l + 32];
        }
        __half* orow = out + ((size_t)(b * NN + n)) * DIMM + h * HDD;
        orow[l] = __float2half_rn(a0 * denom);
        orow[l + 32] = __float2half_rn(a1 * denom);
        __syncwarp();
    }
}

// ---------------- launch ----------------
extern "C" void kernel_launch(void* const* d_in, const int* in_sizes, int n_in,
                              void* d_out, int out_size) {
    const float* query = (const float*)d_in[0];
    const float* key   = (const float*)d_in[1];
    const float* value = (const float*)d_in[2];
    const float* Wq = (const float*)d_in[3];
    const float* bq = (const float*)d_in[4];
    const float* Wk = (const float*)d_in[5];
    const float* bk = (const float*)d_in[6];
    const float* Wv = (const float*)d_in[7];
    const float* bv = (const float*)d_in[8];
    const float* Wo = (const float*)d_in[9];
    const float* bo = (const float*)d_in[10];
    const int* mask = (const int*)d_in[11];

    float *KVPp, *KSPp, *KVp, *KSp;
    __half *hq, *hk, *hv, *Q16, *K16, *V16, *hA, *Wh;
    cudaGetSymbolAddress((void**)&hq, g_hq);
    cudaGetSymbolAddress((void**)&hk, g_hk);
    cudaGetSymbolAddress((void**)&hv, g_hv);
    cudaGetSymbolAddress((void**)&Q16, g_Q16);
    cudaGetSymbolAddress((void**)&K16, g_K16);
    cudaGetSymbolAddress((void**)&V16, g_V16);
    cudaGetSymbolAddress((void**)&hA, g_hA);
    cudaGetSymbolAddress((void**)&Wh, g_Wh);
    cudaGetSymbolAddress((void**)&KVPp, g_kvp);
    cudaGetSymbolAddress((void**)&KSPp, g_ksp);
    cudaGetSymbolAddress((void**)&KVp, g_kv);
    cudaGetSymbolAddress((void**)&KSp, g_ksum);

    cudaFuncSetAttribute(gemm_qkv, cudaFuncAttributeMaxDynamicSharedMemorySize, GEMM_DSMEM);
    cudaFuncSetAttribute(gemm_one, cudaFuncAttributeMaxDynamicSharedMemorySize, GEMM_DSMEM);

    dim3 ggrid3(DIMM / 128, MM / 128, 3);   // (8, 128, 3) = 3072 blocks
    dim3 ggrid(DIMM / 128, MM / 128);

    // 1-2: fp16 conversion passes
    cvt_w4<<<dim3(1024, 4), 256>>>(Wq, Wk, Wv, Wo, Wh);
    cvt_acts<<<dim3(16384, 3), 256>>>(query, key, value, hq, hk, hv);
    // 3: merged Q/K/V projections
    gemm_qkv<<<ggrid3, 256, GEMM_DSMEM>>>(hq, hk, hv, Wh, bq, bk, bv, mask, Q16, K16, V16);
    // 4-5: kv + reduce
    kv_h<<<dim3(KVC, 64), 128>>>(K16, V16, KVPp, KSPp);
    reduce_kv<<<64, 256>>>(KVPp, KSPp, KVp, KSp);
    // 6: attention  <-- ncu profile slot
    attn_kernel<<<dim3(32, 64), 256>>>(Q16, KVp, KSp, hA);
    // 7: output projection
    gemm_one<<<ggrid, 256, GEMM_DSMEM>>>(hA, Wh + 3 * (size_t)DIMM * DIMM, bo, (float*)d_out);
}